// round 6
// baseline (speedup 1.0000x reference)
#include <cuda_runtime.h>

#define W 15            // attention block length
#define DIM 64          // head dim
#define WARPS_PER_CTA 4
#define NTHREADS 128
#define EPS 1e-6f
#define PHI 0.10471975511965977f   // pi/30

typedef unsigned long long ull;

__device__ __forceinline__ ull pack2(float lo, float hi) {
    ull r; asm("mov.b64 %0, {%1,%2};" : "=l"(r) : "f"(lo), "f"(hi)); return r;
}
__device__ __forceinline__ void unpack2(ull v, float& lo, float& hi) {
    asm("mov.b64 {%0,%1}, %2;" : "=f"(lo), "=f"(hi) : "l"(v));
}
__device__ __forceinline__ ull fma2(ull a, ull b, ull c) {
    ull d; asm("fma.rn.f32x2 %0, %1, %2, %3;" : "=l"(d) : "l"(a), "l"(b), "l"(c)); return d;
}
__device__ __forceinline__ ull mul2(ull a, ull b) {
    ull d; asm("mul.rn.f32x2 %0, %1, %2;" : "=l"(d) : "l"(a), "l"(b)); return d;
}
__device__ __forceinline__ float shxor(float v, int m) {
    return __shfl_xor_sync(0xffffffffu, v, m, 32);
}

// cos(phi), sin(phi) for table recurrence
#define CA1 0.9945218953682733f
#define SA1 0.1045284632676535f

__global__ void __launch_bounds__(NTHREADS, 4)
robust_attn_kernel(const float* __restrict__ q, const float* __restrict__ k,
                   const float* __restrict__ v, float* __restrict__ out, int G)
{
    const int wid = blockIdx.x * WARPS_PER_CTA + (threadIdx.x >> 5);
    if (wid >= G) return;

    const int lane = threadIdx.x & 31;
    const int g = lane & 3;       // row-group: rows g, g+4, g+8, g+12
    const int d = lane >> 2;      // dim-group: dims [8d, 8d+8)
    const size_t base = (size_t)wid * (W * DIM);
    const int doff = d * 8;

    // ---- per-lane coefficient table: cd[mi] = cos((g + mi - 3)*phi), zeroed
    //      where g+mi-3 < 0 (encodes causality for ambiguous events). ----
    float cd[16];
    {
        float a0 = ((float)g - 3.0f) * PHI;
        float c = cosf(a0), s = sinf(a0);
        cd[0] = (g >= 3) ? c : 0.f;                 // m = -3
        #pragma unroll
        for (int mi = 1; mi < 16; ++mi) {
            float c2 = c * CA1 - s * SA1;           // rotate +phi
            s = s * CA1 + c * SA1;
            c = c2;
            int delta = g + mi - 3;
            cd[mi] = (delta >= 0) ? c : 0.f;
        }
    }

    // ---- load + relu q slices for my 4 rows (row 15 clamped; masked at store) ----
    ull q2[4][4];
    #pragma unroll
    for (int t = 0; t < 4; ++t) {
        int row = g + 4 * t; if (row > W - 1) row = W - 1;
        const float4* qp = (const float4*)(q + base + row * DIM + doff);
        float4 a = qp[0], b = qp[1];
        q2[t][0] = pack2(fmaxf(a.x, 0.f), fmaxf(a.y, 0.f));
        q2[t][1] = pack2(fmaxf(a.z, 0.f), fmaxf(a.w, 0.f));
        q2[t][2] = pack2(fmaxf(b.x, 0.f), fmaxf(b.y, 0.f));
        q2[t][3] = pack2(fmaxf(b.z, 0.f), fmaxf(b.w, 0.f));
    }

    ull acc[4][4];
    #pragma unroll
    for (int t = 0; t < 4; ++t)
        #pragma unroll
        for (int e = 0; e < 4; ++e) acc[t][e] = 0ULL;
    float dn[4] = {0.f, 0.f, 0.f, 0.f};

    // ---- fused pass over j: K,V read once per warp (4x lane broadcast) ----
    #pragma unroll
    for (int j = 0; j < W; ++j) {
        const int nt = (j <= 3) ? 0 : (j <= 7) ? 1 : (j <= 11) ? 2 : 3;

        // K loads + relu/pack
        const float4* kp = (const float4*)(k + base + j * DIM + doff);
        float4 k0 = kp[0], k1 = kp[1];
        ull ka = pack2(fmaxf(k0.x, 0.f), fmaxf(k0.y, 0.f));
        ull kb = pack2(fmaxf(k0.z, 0.f), fmaxf(k0.w, 0.f));
        ull kc = pack2(fmaxf(k1.x, 0.f), fmaxf(k1.y, 0.f));
        ull kd = pack2(fmaxf(k1.z, 0.f), fmaxf(k1.w, 0.f));

        // independent dot chains for active t's
        float pf[4];
        #pragma unroll
        for (int t = 0; t < 4; ++t) {
            if (t >= nt) {
                ull a = mul2(q2[t][0], ka);
                a = fma2(q2[t][1], kb, a);
                a = fma2(q2[t][2], kc, a);
                a = fma2(q2[t][3], kd, a);
                float pl, ph; unpack2(a, pl, ph);
                pf[t] = pl + ph;
            }
        }

        // V loads issued before the shuffle burst (latency overlapped)
        const float4* vp = (const float4*)(v + base + j * DIM + doff);
        float4 v0 = vp[0], v1 = vp[1];

        // batched independent 3-round reductions over the 8 dim-groups
        #pragma unroll
        for (int t = nt; t < 4; ++t) pf[t] += shxor(pf[t], 4);
        #pragma unroll
        for (int t = nt; t < 4; ++t) pf[t] += shxor(pf[t], 8);
        #pragma unroll
        for (int t = nt; t < 4; ++t) pf[t] += shxor(pf[t], 16);

        ull va = pack2(fmaxf(v0.x, 0.f), fmaxf(v0.y, 0.f));
        ull vb = pack2(fmaxf(v0.z, 0.f), fmaxf(v0.w, 0.f));
        ull vc = pack2(fmaxf(v1.x, 0.f), fmaxf(v1.y, 0.f));
        ull vd = pack2(fmaxf(v1.z, 0.f), fmaxf(v1.w, 0.f));

        // scale by table constant (causality pre-baked as zeros), accumulate
        #pragma unroll
        for (int t = 0; t < 4; ++t) {
            if (t >= nt) {
                float s = pf[t] * cd[4 * t - j + 3];   // compile-time index
                dn[t] += s;
                ull s2 = pack2(s, s);
                acc[t][0] = fma2(s2, va, acc[t][0]);
                acc[t][1] = fma2(s2, vb, acc[t][1]);
                acc[t][2] = fma2(s2, vc, acc[t][2]);
                acc[t][3] = fma2(s2, vd, acc[t][3]);
            }
        }
    }

    // ---- normalize + store ----
    #pragma unroll
    for (int t = 0; t < 4; ++t) {
        int row = g + 4 * t;
        if (row < W) {
            float rdt = __fdividef(1.0f, fmaxf(dn[t], EPS));
            ull r2 = pack2(rdt, rdt);
            ulonglong2 o0, o1;
            o0.x = mul2(acc[t][0], r2); o0.y = mul2(acc[t][1], r2);
            o1.x = mul2(acc[t][2], r2); o1.y = mul2(acc[t][3], r2);
            ulonglong2* op = (ulonglong2*)(out + base + row * DIM + doff);
            op[0] = o0; op[1] = o1;
        }
    }
}

extern "C" void kernel_launch(void* const* d_in, const int* in_sizes, int n_in,
                              void* d_out, int out_size) {
    const float* q = (const float*)d_in[0];
    const float* k = (const float*)d_in[1];
    const float* v = (const float*)d_in[2];
    float* out = (float*)d_out;

    int n = in_sizes[0];            // B*H*L*D
    int G = n / (W * DIM);          // number of attention blocks (20480)
    int grid = (G + WARPS_PER_CTA - 1) / WARPS_PER_CTA;
    robust_attn_kernel<<<grid, NTHREADS>>>(q, k, v, out, G);
}

// round 7
// speedup vs baseline: 1.4306x; 1.4306x over previous
#include <cuda_runtime.h>

#define W 15            // attention block length
#define DIM 64          // head dim
#define BLK_PER_CTA 4   // one block per warp
#define NTHREADS 128
#define EPS 1e-6f

typedef unsigned long long ull;

__device__ __forceinline__ ull pack2(float lo, float hi) {
    ull r; asm("mov.b64 %0, {%1,%2};" : "=l"(r) : "f"(lo), "f"(hi)); return r;
}
__device__ __forceinline__ void unpack2(ull v, float& lo, float& hi) {
    asm("mov.b64 {%0,%1}, %2;" : "=f"(lo), "=f"(hi) : "l"(v));
}
__device__ __forceinline__ ull fma2(ull a, ull b, ull c) {
    ull d; asm("fma.rn.f32x2 %0, %1, %2, %3;" : "=l"(d) : "l"(a), "l"(b), "l"(c)); return d;
}
__device__ __forceinline__ ull mul2(ull a, ull b) {
    ull d; asm("mul.rn.f32x2 %0, %1, %2;" : "=l"(d) : "l"(a), "l"(b)); return d;
}
__device__ __forceinline__ float shxor(float v, int m) {
    return __shfl_xor_sync(0xffffffffu, v, m, 32);
}

// angle-step literals (phi = pi/30)
#define CA1 0.9945218953682733f   // cos(phi)
#define SA1 0.1045284632676535f   // sin(phi)
#define CA4 0.9135454576426009f   // cos(4*phi)
#define SA4 0.4067366430758002f   // sin(4*phi)
#define CG2 0.9781476007338057f   // cos(2*phi)
#define SG2 0.2079116908177593f
#define CG3 0.9510565162951535f   // cos(3*phi)
#define SG3 0.3090169943749474f

__global__ void __launch_bounds__(NTHREADS)
robust_attn_kernel(const float* __restrict__ q, const float* __restrict__ k,
                   const float* __restrict__ v, float* __restrict__ out, int G)
{
    // relu'd K,V for the CTA's 4 blocks, gmem-contiguous layout (no pad).
    __shared__ float sK[BLK_PER_CTA * W * DIM];   // 3840 floats
    __shared__ float sV[BLK_PER_CTA * W * DIM];

    const int tid = threadIdx.x;
    const int blk0 = blockIdx.x * BLK_PER_CTA;
    const int nvalid = min(BLK_PER_CTA, G - blk0);
    const int nf4 = nvalid * (W * DIM / 4);       // valid float4 count (<=960)
    const size_t base0 = (size_t)blk0 * (W * DIM);

    // ---- one-shot fill: 16 batched LDG.128, relu at store ----
    {
        const float4* gk = (const float4*)(k + base0);
        const float4* gv = (const float4*)(v + base0);
        float4 tk[8], tv[8];
        #pragma unroll
        for (int it = 0; it < 8; ++it) {
            int i4 = it * NTHREADS + tid;
            if (i4 < nf4) { tk[it] = gk[i4]; tv[it] = gv[i4]; }
        }
        #pragma unroll
        for (int it = 0; it < 8; ++it) {
            int i4 = it * NTHREADS + tid;
            if (i4 < nf4) {
                float4 a = tk[it];
                a.x = fmaxf(a.x, 0.f); a.y = fmaxf(a.y, 0.f);
                a.z = fmaxf(a.z, 0.f); a.w = fmaxf(a.w, 0.f);
                *(float4*)&sK[i4 * 4] = a;
                float4 b = tv[it];
                b.x = fmaxf(b.x, 0.f); b.y = fmaxf(b.y, 0.f);
                b.z = fmaxf(b.z, 0.f); b.w = fmaxf(b.w, 0.f);
                *(float4*)&sV[i4 * 4] = b;
            }
        }
    }

    const int warp = tid >> 5;
    const int lane = tid & 31;
    const int g = lane & 3;       // row-group: rows g, g+4, g+8, g+12
    const int d = lane >> 2;      // dim-group: dims [8d, 8d+8)
    const int doff = d * 8;
    const int blk = blk0 + warp;
    const int blkc = (blk < G) ? blk : (G - 1);
    const size_t base = (size_t)blkc * (W * DIM);

    // ---- per-lane cos/sin of own row angles (as R2) ----
    float cg = (g == 0) ? 1.0f : (g == 1) ? CA1 : (g == 2) ? CG2 : CG3;
    float sg = (g == 0) ? 0.0f : (g == 1) ? SA1 : (g == 2) ? SG2 : SG3;
    float ci[4], si[4];
    ci[0] = cg; si[0] = sg;
    #pragma unroll
    for (int t = 1; t < 4; ++t) {
        ci[t] = ci[t-1] * CA4 - si[t-1] * SA4;
        si[t] = si[t-1] * CA4 + ci[t-1] * SA4;
    }

    // ---- load + relu q slices for my 4 rows (overlaps with fill) ----
    ull q2[4][4];
    #pragma unroll
    for (int t = 0; t < 4; ++t) {
        int row = g + 4 * t; if (row > W - 1) row = W - 1;
        const float4* qp = (const float4*)(q + base + row * DIM + doff);
        float4 a = qp[0], b = qp[1];
        q2[t][0] = pack2(fmaxf(a.x, 0.f), fmaxf(a.y, 0.f));
        q2[t][1] = pack2(fmaxf(a.z, 0.f), fmaxf(a.w, 0.f));
        q2[t][2] = pack2(fmaxf(b.x, 0.f), fmaxf(b.y, 0.f));
        q2[t][3] = pack2(fmaxf(b.z, 0.f), fmaxf(b.w, 0.f));
    }

    __syncthreads();
    if (blk >= G) return;

    ull acc[4][4];
    #pragma unroll
    for (int t = 0; t < 4; ++t)
        #pragma unroll
        for (int e = 0; e < 4; ++e) acc[t][e] = 0ULL;
    float dn[4] = {0.f, 0.f, 0.f, 0.f};

    const int sbase = warp * (W * DIM) + doff;

    // ---- fused pass over j: packed relu'd K,V from smem (29-cyc LDS) ----
    float cj = 1.0f, sj = 0.0f;   // cos/sin(j*phi)
    #pragma unroll
    for (int j = 0; j < W; ++j) {
        const ulonglong2* kp = (const ulonglong2*)&sK[sbase + j * DIM];
        ulonglong2 kA = kp[0], kB = kp[1];
        const ulonglong2* vp = (const ulonglong2*)&sV[sbase + j * DIM];
        ulonglong2 vA = vp[0], vB = vp[1];

        #pragma unroll
        for (int t = 0; t < 4; ++t) {
            if (4 * t + 3 >= j) {          // compile-time skip of impossible pairs
                ull a = mul2(q2[t][0], kA.x);
                a = fma2(q2[t][1], kA.y, a);
                a = fma2(q2[t][2], kB.x, a);
                a = fma2(q2[t][3], kB.y, a);
                float pl, ph; unpack2(a, pl, ph);
                float pf = pl + ph;
                pf += shxor(pf, 4);
                pf += shxor(pf, 8);
                pf += shxor(pf, 16);
                float s = pf * (ci[t] * cj + si[t] * sj);
                if (4 * t < j) s = (g >= j - 4 * t) ? s : 0.f;
                dn[t] += s;
                ull s2 = pack2(s, s);
                acc[t][0] = fma2(s2, vA.x, acc[t][0]);
                acc[t][1] = fma2(s2, vA.y, acc[t][1]);
                acc[t][2] = fma2(s2, vB.x, acc[t][2]);
                acc[t][3] = fma2(s2, vB.y, acc[t][3]);
            }
        }
        float cjn = cj * CA1 - sj * SA1;
        sj = sj * CA1 + cj * SA1;
        cj = cjn;
    }

    // ---- normalize + store ----
    #pragma unroll
    for (int t = 0; t < 4; ++t) {
        int row = g + 4 * t;
        if (row < W) {
            float rdt = __fdividef(1.0f, fmaxf(dn[t], EPS));
            ull r2 = pack2(rdt, rdt);
            ulonglong2 o0, o1;
            o0.x = mul2(acc[t][0], r2); o0.y = mul2(acc[t][1], r2);
            o1.x = mul2(acc[t][2], r2); o1.y = mul2(acc[t][3], r2);
            ulonglong2* op = (ulonglong2*)(out + base + row * DIM + doff);
            op[0] = o0; op[1] = o1;
        }
    }
}

extern "C" void kernel_launch(void* const* d_in, const int* in_sizes, int n_in,
                              void* d_out, int out_size) {
    const float* q = (const float*)d_in[0];
    const float* k = (const float*)d_in[1];
    const float* v = (const float*)d_in[2];
    float* out = (float*)d_out;

    int n = in_sizes[0];            // B*H*L*D
    int G = n / (W * DIM);          // number of attention blocks (20480)
    int grid = (G + BLK_PER_CTA - 1) / BLK_PER_CTA;
    robust_attn_kernel<<<grid, NTHREADS>>>(q, k, v, out, G);
}

// round 8
// speedup vs baseline: 1.4650x; 1.0241x over previous
#include <cuda_runtime.h>

#define W 15            // attention block length
#define DIM 64          // head dim
#define BLK_PER_CTA 4   // one block per warp
#define NTHREADS 128
#define EPS 1e-6f

typedef unsigned long long ull;

__device__ __forceinline__ ull pack2(float lo, float hi) {
    ull r; asm("mov.b64 %0, {%1,%2};" : "=l"(r) : "f"(lo), "f"(hi)); return r;
}
__device__ __forceinline__ void unpack2(ull v, float& lo, float& hi) {
    asm("mov.b64 {%0,%1}, %2;" : "=f"(lo), "=f"(hi) : "l"(v));
}
__device__ __forceinline__ ull fma2(ull a, ull b, ull c) {
    ull d; asm("fma.rn.f32x2 %0, %1, %2, %3;" : "=l"(d) : "l"(a), "l"(b), "l"(c)); return d;
}
__device__ __forceinline__ ull mul2(ull a, ull b) {
    ull d; asm("mul.rn.f32x2 %0, %1, %2;" : "=l"(d) : "l"(a), "l"(b)); return d;
}
__device__ __forceinline__ float shxor(float v, int m) {
    return __shfl_xor_sync(0xffffffffu, v, m, 32);
}

// angle-step literals (phi = pi/30)
#define CA1 0.9945218953682733f   // cos(phi)
#define SA1 0.1045284632676535f   // sin(phi)
#define CA4 0.9135454576426009f   // cos(4*phi)
#define SA4 0.4067366430758002f   // sin(4*phi)
#define CG2 0.9781476007338057f   // cos(2*phi)
#define SG2 0.2079116908177593f
#define CG3 0.9510565162951535f   // cos(3*phi)
#define SG3 0.3090169943749474f

__global__ void __launch_bounds__(NTHREADS, 5)
robust_attn_kernel(const float* __restrict__ q, const float* __restrict__ k,
                   const float* __restrict__ v, float* __restrict__ out, int G)
{
    // relu'd K,V; each warp owns a private 960-float region (no barrier needed)
    __shared__ float sK[BLK_PER_CTA * W * DIM];
    __shared__ float sV[BLK_PER_CTA * W * DIM];

    const int tid = threadIdx.x;
    const int warp = tid >> 5;
    const int lane = tid & 31;
    const int blk = blockIdx.x * BLK_PER_CTA + warp;
    if (blk >= G) return;                       // safe: no CTA-wide sync anywhere
    const size_t base = (size_t)blk * (W * DIM);

    // ---- per-warp fill of own block: 16 batched LDG.128, relu at store ----
    {
        const float4* gk = (const float4*)(k + base);
        const float4* gv = (const float4*)(v + base);
        float4 tk[8], tv[8];
        #pragma unroll
        for (int it = 0; it < 8; ++it) {
            int i4 = it * 32 + lane;            // 0..255, valid < 240
            bool ok = (it < 7) || (lane < 16);
            if (ok) { tk[it] = gk[i4]; tv[it] = gv[i4]; }
        }
        float* wK = &sK[warp * (W * DIM)];
        float* wV = &sV[warp * (W * DIM)];
        #pragma unroll
        for (int it = 0; it < 8; ++it) {
            int i4 = it * 32 + lane;
            bool ok = (it < 7) || (lane < 16);
            if (ok) {
                float4 a = tk[it];
                a.x = fmaxf(a.x, 0.f); a.y = fmaxf(a.y, 0.f);
                a.z = fmaxf(a.z, 0.f); a.w = fmaxf(a.w, 0.f);
                *(float4*)&wK[i4 * 4] = a;
                float4 b = tv[it];
                b.x = fmaxf(b.x, 0.f); b.y = fmaxf(b.y, 0.f);
                b.z = fmaxf(b.z, 0.f); b.w = fmaxf(b.w, 0.f);
                *(float4*)&wV[i4 * 4] = b;
            }
        }
    }

    const int g = lane & 3;       // row-group: rows g, g+4, g+8, g+12
    const int d = lane >> 2;      // dim-group: dims [8d, 8d+8)
    const int doff = d * 8;

    // ---- per-lane cos/sin of own row angles ----
    float cg = (g == 0) ? 1.0f : (g == 1) ? CA1 : (g == 2) ? CG2 : CG3;
    float sg = (g == 0) ? 0.0f : (g == 1) ? SA1 : (g == 2) ? SG2 : SG3;
    float ci[4], si[4];
    ci[0] = cg; si[0] = sg;
    #pragma unroll
    for (int t = 1; t < 4; ++t) {
        ci[t] = ci[t-1] * CA4 - si[t-1] * SA4;
        si[t] = si[t-1] * CA4 + ci[t-1] * SA4;
    }

    // ---- load + relu q slices for my 4 rows (overlaps syncwarp window) ----
    ull q2[4][4];
    #pragma unroll
    for (int t = 0; t < 4; ++t) {
        int row = g + 4 * t; if (row > W - 1) row = W - 1;
        const float4* qp = (const float4*)(q + base + row * DIM + doff);
        float4 a = qp[0], b = qp[1];
        q2[t][0] = pack2(fmaxf(a.x, 0.f), fmaxf(a.y, 0.f));
        q2[t][1] = pack2(fmaxf(a.z, 0.f), fmaxf(a.w, 0.f));
        q2[t][2] = pack2(fmaxf(b.x, 0.f), fmaxf(b.y, 0.f));
        q2[t][3] = pack2(fmaxf(b.z, 0.f), fmaxf(b.w, 0.f));
    }

    __syncwarp();

    ull acc[4][4];
    #pragma unroll
    for (int t = 0; t < 4; ++t)
        #pragma unroll
        for (int e = 0; e < 4; ++e) acc[t][e] = 0ULL;
    float dn[4] = {0.f, 0.f, 0.f, 0.f};

    const int sbase = warp * (W * DIM) + doff;

    // ---- fused pass over j: packed relu'd K,V from smem (29-cyc LDS) ----
    float cj = 1.0f, sj = 0.0f;   // cos/sin(j*phi)
    #pragma unroll
    for (int j = 0; j < W; ++j) {
        const ulonglong2* kp = (const ulonglong2*)&sK[sbase + j * DIM];
        ulonglong2 kA = kp[0], kB = kp[1];
        const ulonglong2* vp = (const ulonglong2*)&sV[sbase + j * DIM];
        ulonglong2 vA = vp[0], vB = vp[1];

        #pragma unroll
        for (int t = 0; t < 4; ++t) {
            if (4 * t + 3 >= j) {          // compile-time skip of impossible pairs
                ull a = mul2(q2[t][0], kA.x);
                a = fma2(q2[t][1], kA.y, a);
                a = fma2(q2[t][2], kB.x, a);
                a = fma2(q2[t][3], kB.y, a);
                float pl, ph; unpack2(a, pl, ph);
                float pf = pl + ph;
                pf += shxor(pf, 4);
                pf += shxor(pf, 8);
                pf += shxor(pf, 16);
                float s = pf * (ci[t] * cj + si[t] * sj);
                if (4 * t < j) s = (g >= j - 4 * t) ? s : 0.f;
                dn[t] += s;
                ull s2 = pack2(s, s);
                acc[t][0] = fma2(s2, vA.x, acc[t][0]);
                acc[t][1] = fma2(s2, vA.y, acc[t][1]);
                acc[t][2] = fma2(s2, vB.x, acc[t][2]);
                acc[t][3] = fma2(s2, vB.y, acc[t][3]);
            }
        }
        float cjn = cj * CA1 - sj * SA1;
        sj = sj * CA1 + cj * SA1;
        cj = cjn;
    }

    // ---- normalize + store ----
    #pragma unroll
    for (int t = 0; t < 4; ++t) {
        int row = g + 4 * t;
        if (row < W) {
            float rdt = __fdividef(1.0f, fmaxf(dn[t], EPS));
            ull r2 = pack2(rdt, rdt);
            ulonglong2 o0, o1;
            o0.x = mul2(acc[t][0], r2); o0.y = mul2(acc[t][1], r2);
            o1.x = mul2(acc[t][2], r2); o1.y = mul2(acc[t][3], r2);
            ulonglong2* op = (ulonglong2*)(out + base + row * DIM + doff);
            op[0] = o0; op[1] = o1;
        }
    }
}

extern "C" void kernel_launch(void* const* d_in, const int* in_sizes, int n_in,
                              void* d_out, int out_size) {
    const float* q = (const float*)d_in[0];
    const float* k = (const float*)d_in[1];
    const float* v = (const float*)d_in[2];
    float* out = (float*)d_out;

    int n = in_sizes[0];            // B*H*L*D
    int G = n / (W * DIM);          // number of attention blocks (20480)
    int grid = (G + BLK_PER_CTA - 1) / BLK_PER_CTA;
    robust_attn_kernel<<<grid, NTHREADS>>>(q, k, v, out, G);
}